// round 13
// baseline (speedup 1.0000x reference)
#include <cuda_runtime.h>
#include <cuda_fp16.h>
#include <cstdint>

#define N_GAUSS   16
#define N_ATOMS   3072
#define N_GRAPHS  64
#define K_GRID    4096

// Table: per atom, 512 cubic intervals over t = 8*r2. Interval i = round(t)
// covers t in [i-0.5, i+0.5]; local parameter u = t - i in [-0.5, 0.5].
// Entry = 4 coefficients quantized to fp16, packed in uint2 (8 bytes).
#define NNODES    512
#define TSCALE    8.0f
#define ABYTES    (NNODES * 8)      // 4 KB per atom table

#define BLOCK     256
#define PPT       4
#define CHUNK     (BLOCK*PPT)       // 1024
#define NCHUNK    (K_GRID/CHUNK)    // 4
#define ASPLIT    4                 // -> 1024 blocks

#define NTAB      4                 // atoms per tile buffer
#define SMEM_DYN  (2 * NTAB * ABYTES)   // 32 KB (double buffer)
#define ACAP      128

__device__ uint2 g_table[N_ATOMS * NNODES];   // ~12 MB scratch
__device__ int   g_start[N_GRAPHS + 1];

__device__ __forceinline__ float ex2f(float x) {
    float y; asm("ex2.approx.ftz.f32 %0, %1;" : "=f"(y) : "f"(x)); return y;
}
__device__ __forceinline__ uint32_t s2u(const void* p) {
    return (uint32_t)__cvta_generic_to_shared(p);
}
__device__ __forceinline__ void mbar_init(uint32_t a, uint32_t cnt) {
    asm volatile("mbarrier.init.shared.b64 [%0], %1;" :: "r"(a), "r"(cnt) : "memory");
}
__device__ __forceinline__ void mbar_expect_tx(uint32_t a, uint32_t tx) {
    asm volatile("mbarrier.arrive.expect_tx.shared.b64 _, [%0], %1;" :: "r"(a), "r"(tx) : "memory");
}
__device__ __forceinline__ void bulk_g2s(uint32_t dst, const void* src,
                                         uint32_t sz, uint32_t mbar) {
    asm volatile("cp.async.bulk.shared::cluster.global.mbarrier::complete_tx::bytes"
                 " [%0], [%1], %2, [%3];"
                 :: "r"(dst), "l"(src), "r"(sz), "r"(mbar) : "memory");
}
// HW-sleep wait: the 0x989680 suspend hint parks the warp instead of
// busy-spinning, freeing issue slots for co-resident warps.
__device__ __forceinline__ void mbar_wait(uint32_t mbar, uint32_t phase) {
    asm volatile(
        "{\n\t"
        ".reg .pred P;\n\t"
        "WAIT_%=:\n\t"
        "mbarrier.try_wait.parity.acquire.cta.shared::cta.b64 P, [%0], %1, 0x989680;\n\t"
        "@P bra.uni DONE_%=;\n\t"
        "bra.uni WAIT_%=;\n\t"
        "DONE_%=:\n\t"
        "}" :: "r"(mbar), "r"(phase) : "memory");
}

// ---------------------------------------------------------------------------
// Build: per-atom fp16 Hermite-cubic table (geometric exp recurrence).
// Extra duties: zero the output array (blocks 0..2047); block 0 computes
// g_start[] from batch (dtype-detect + transition scan, disjoint writers).
__global__ __launch_bounds__(128)
void build_kernel(const float* __restrict__ coeff,
                  const int* __restrict__ braw,
                  float* __restrict__ out) {
    const int atom = blockIdx.x;
    const int tid  = threadIdx.x;
    __shared__ float w[N_GAUSS], wc[N_GAUSS], fstep[N_GAUSS];
    __shared__ float fv[NNODES + 1], mv[NNODES + 1];
    __shared__ int s_flag;

    // Zero output: 2048 blocks x 128 threads = 262144 = 64*4096 elements.
    if (atom < (N_GRAPHS * K_GRID) / 128)
        out[atom * 128 + tid] = 0.0f;

    // Block 0: compute g_start from batch.
    if (atom == 0) {
        if (tid == 0) s_flag = 0;
        __syncthreads();
        int loc = 0;
        for (int i = 1 + 2 * tid; i < N_ATOMS; i += 2 * 128) loc |= braw[i];
        if (loc) atomicOr(&s_flag, 1);
        __syncthreads();
        const bool is32 = (s_flag != 0);
        for (int i = tid; i < N_ATOMS; i += 128) {
            int bi = is32 ? braw[i] : braw[2 * i];
            int bp = (i == 0) ? -1 : (is32 ? braw[i - 1] : braw[2 * i - 2]);
            for (int gg = bp + 1; gg <= bi; gg++) g_start[gg] = i;
            if (i == N_ATOMS - 1)
                for (int gg = bi + 1; gg <= N_GRAPHS; gg++) g_start[gg] = N_ATOMS;
        }
    }

    if (tid < N_GAUSS) {
        int j = tid;
        float sigma = 0.5f + 0.3f * (float)j;
        float tt = sigma * 2.5066282746310002f;      // sigma*sqrt(2*pi)
        float sr = 1.0f / (tt * tt * tt);
        float cj = 1.0f / (sigma * sigma);
        float wj = coeff[atom * N_GAUSS + j] * sr;
        w[j]  = wj;
        wc[j] = wj * cj * (1.0f / TSCALE);           // df/dt = -sum wc*e
        float cL = 1.4426950408889634f * cj;
        fstep[j] = ex2f(-cL * (1.0f / TSCALE));
    }
    __syncthreads();

    {
        const int k0 = 4 * tid;                      // nodes k0..k0+3
        float s1[4] = {0.f, 0.f, 0.f, 0.f};
        float s2[4] = {0.f, 0.f, 0.f, 0.f};
        const float r20 = ((float)k0 - 0.5f) * (1.0f / TSCALE);
        #pragma unroll
        for (int j = 0; j < N_GAUSS; j++) {
            float sigma = 0.5f + 0.3f * (float)j;
            float cL = 1.4426950408889634f / (sigma * sigma);
            float e  = ex2f(-r20 * cL);
            const float f = fstep[j];
            const float wj = w[j], wcj = wc[j];
            #pragma unroll
            for (int m = 0; m < 4; m++) {
                s1[m] = fmaf(wj,  e, s1[m]);
                s2[m] = fmaf(wcj, e, s2[m]);
                e *= f;
            }
        }
        #pragma unroll
        for (int m = 0; m < 4; m++) { fv[k0 + m] = s1[m]; mv[k0 + m] = -s2[m]; }
    }
    if (tid == 0) {                                  // node 512 tail
        float r2 = 511.5f * (1.0f / TSCALE);
        float s1 = 0.f, s2 = 0.f;
        #pragma unroll
        for (int j = 0; j < N_GAUSS; j++) {
            float sigma = 0.5f + 0.3f * (float)j;
            float cL = 1.4426950408889634f / (sigma * sigma);
            float e = ex2f(-r2 * cL);
            s1 = fmaf(w[j],  e, s1);
            s2 = fmaf(wc[j], e, s2);
        }
        fv[NNODES] = s1; mv[NNODES] = -s2;
    }
    __syncthreads();

    for (int i = tid; i < NNODES; i += 128) {
        float fL = fv[i], fR = fv[i + 1];
        float mL = mv[i], mR = mv[i + 1];
        float dd = fR - fL;
        float a0 = fL, a1 = mL;
        float a2 = 3.0f * dd - 2.0f * mL - mR;
        float a3 = mL + mR - 2.0f * dd;
        // Shift Hermite basis v in [0,1] -> u = v-0.5 in [-0.5,0.5]:
        float c0 = a0 + 0.5f * a1 + 0.25f * a2 + 0.125f * a3;
        float c1 = a1 + a2 + 0.75f * a3;
        float c2 = a2 + 1.5f * a3;
        float c3 = a3;
        __half2 h01 = __floats2half2_rn(c0, c1);
        __half2 h23 = __floats2half2_rn(c2, c3);
        uint2 e;
        e.x = *reinterpret_cast<uint32_t*>(&h01);
        e.y = *reinterpret_cast<uint32_t*>(&h23);
        g_table[(size_t)atom * NNODES + i] = e;
    }
}

// ---------------------------------------------------------------------------
// Density: 1024 blocks (4 chunks x 64 graphs x 4 atom-splits), 256 threads,
// 4 points/thread. 4-atom fp16 tables per tile, double-buffered bulk copies.
// Index clamp on the integer side; u = t - round(t) is valid for any t.
__global__ __launch_bounds__(BLOCK, 6)
void density_kernel(const float* __restrict__ atom_coord,
                    const float* __restrict__ grid,
                    float* __restrict__ out) {
    extern __shared__ __align__(16) uint2 tbl[];    // [2][NTAB][NNODES]
    __shared__ float  sax[ACAP], say[ACAP], saz[ACAP];
    __shared__ __align__(8) unsigned long long mbar[2];

    const int g   = blockIdx.y;
    const int tid = threadIdx.x;
    const uint32_t mb0 = s2u(&mbar[0]);
    const uint32_t mb1 = s2u(&mbar[1]);

    if (tid == 0) {
        mbar_init(mb0, 1);
        mbar_init(mb1, 1);
        asm volatile("fence.proxy.async.shared::cta;" ::: "memory");
    }

    // Per-graph atom range (precomputed by build_kernel block 0).
    const int s0    = g_start[g];
    const int n_all = g_start[g + 1] - s0;
    const int part  = (n_all + ASPLIT - 1) / ASPLIT;
    const int aoff  = blockIdx.z * part;
    const int start = s0 + aoff;
    const int n     = min(n_all - aoff, part);

    const float S = 2.8284271247461903f;  // sqrt(8): t = |S*(p-a)|^2 = 8*r2
    const float* gp = grid + (size_t)g * K_GRID * 3;
    const int kb = blockIdx.x * CHUNK + tid;

    float px[PPT], py[PPT], pz[PPT], acc[PPT];
    #pragma unroll
    for (int q = 0; q < PPT; q++) {
        const int k = kb + q * BLOCK;
        px[q] = gp[k * 3 + 0] * S;
        py[q] = gp[k * 3 + 1] * S;
        pz[q] = gp[k * 3 + 2] * S;
        acc[q] = 0.f;
    }

    // Stage coords for this block's range once.
    for (int a = tid; a < n; a += BLOCK) {
        const float* ac = atom_coord + (size_t)(start + a) * 3;
        sax[a] = ac[0] * S;
        say[a] = ac[1] * S;
        saz[a] = ac[2] * S;
    }
    __syncthreads();   // coords + mbar init visible

    const int ntiles = (n + NTAB - 1) / NTAB;
    uint32_t ph0 = 0, ph1 = 0;

    // Prime tiles 0 and 1.
    if (tid == 0) {
        if (ntiles > 0) {
            uint32_t sz = (uint32_t)min(NTAB, n) * ABYTES;
            mbar_expect_tx(mb0, sz);
            bulk_g2s(s2u(tbl), g_table + (size_t)start * NNODES, sz, mb0);
        }
        if (ntiles > 1) {
            uint32_t sz = (uint32_t)min(NTAB, n - NTAB) * ABYTES;
            mbar_expect_tx(mb1, sz);
            bulk_g2s(s2u(tbl + NTAB * NNODES),
                     g_table + (size_t)(start + NTAB) * NNODES, sz, mb1);
        }
    }

    for (int s = 0; s < ntiles; s++) {
        const int buf = s & 1;
        if (buf == 0) { mbar_wait(mb0, ph0); ph0 ^= 1; }
        else          { mbar_wait(mb1, ph1); ph1 ^= 1; }

        const int a0  = s * NTAB;
        const int cnt = min(NTAB, n - a0);
        const char* tb0 = (const char*)(tbl + buf * (NTAB * NNODES));

        #pragma unroll
        for (int a = 0; a < NTAB; a++) {
            if (a < cnt) {
                const float ax = sax[a0 + a], ay = say[a0 + a], az = saz[a0 + a];
                const char* tb = tb0 + a * ABYTES;
                #pragma unroll
                for (int q = 0; q < PPT; q++) {
                    float dx = px[q] - ax, dy = py[q] - ay, dz = pz[q] - az;
                    float t = fmaf(dx, dx, fmaf(dy, dy, dz * dz));
                    float m = t + 8388608.0f;            // round(t) via 2^23
                    // Mantissa low bits == round(t) for t < 2^23; saturate
                    // the index only. u stays in [-0.5,0.5] regardless.
                    int   i = min(__float_as_int(m) & 0x7FFFFF, NNODES - 1);
                    float u = t - (m - 8388608.0f);
                    uint2 e = *reinterpret_cast<const uint2*>(tb + i * 8);
                    float2 c01 = __half22float2(*reinterpret_cast<__half2*>(&e.x));
                    float2 c23 = __half22float2(*reinterpret_cast<__half2*>(&e.y));
                    acc[q] += fmaf(fmaf(fmaf(c23.y, u, c23.x), u, c01.y), u, c01.x);
                }
            }
        }

        __syncthreads();   // all reads of tbl[buf] done before restage
        if (tid == 0 && s + 2 < ntiles) {
            const int an = (s + 2) * NTAB;
            uint32_t sz = (uint32_t)min(NTAB, n - an) * ABYTES;
            uint32_t mb = buf ? mb1 : mb0;
            mbar_expect_tx(mb, sz);
            bulk_g2s(s2u(tbl + buf * (NTAB * NNODES)),
                     g_table + (size_t)(start + an) * NNODES, sz, mb);
        }
    }

    float* op = out + (size_t)g * K_GRID;
    #pragma unroll
    for (int q = 0; q < PPT; q++)
        atomicAdd(&op[kb + q * BLOCK], acc[q]);
}

// ---------------------------------------------------------------------------
extern "C" void kernel_launch(void* const* d_in, const int* in_sizes, int n_in,
                              void* d_out, int out_size) {
    const float* coeff      = (const float*)d_in[0];
    const float* atom_coord = (const float*)d_in[1];
    const float* grid       = (const float*)d_in[2];
    const int*   batch_raw  = (const int*)d_in[3];
    float* out = (float*)d_out;

    static bool attr_done = false;
    if (!attr_done) {
        cudaFuncSetAttribute(density_kernel,
                             cudaFuncAttributeMaxDynamicSharedMemorySize,
                             SMEM_DYN);
        attr_done = true;
    }

    build_kernel<<<N_ATOMS, 128>>>(coeff, batch_raw, out);
    density_kernel<<<dim3(NCHUNK, N_GRAPHS, ASPLIT), BLOCK, SMEM_DYN>>>(
        atom_coord, grid, out);
}

// round 14
// speedup vs baseline: 1.0158x; 1.0158x over previous
#include <cuda_runtime.h>
#include <cuda_fp16.h>
#include <cstdint>

#define N_GAUSS   16
#define N_ATOMS   3072
#define N_GRAPHS  64
#define K_GRID    4096

// Table: per atom, 512 cubic intervals over t = 8*r2. Interval i = round(t)
// covers t in [i-0.5, i+0.5]; local parameter u = t - i in [-0.5, 0.5].
// Entry = 4 coefficients quantized to fp16, packed in uint2 (8 bytes).
#define NNODES    512
#define TSCALE    8.0f
#define ABYTES    (NNODES * 8)      // 4 KB per atom table

#define BLOCK     256
#define PPT       4
#define NPAIR     (PPT/2)
#define CHUNK     (BLOCK*PPT)       // 1024
#define NCHUNK    (K_GRID/CHUNK)    // 4
#define ASPLIT    4                 // -> 1024 blocks

#define NTAB      4                 // atoms per tile buffer
#define SMEM_DYN  (2 * NTAB * ABYTES)   // 32 KB (double buffer)
#define ACAP      128

// Packed f32x2 constants: {2^23, 2^23}, {-2^23, -2^23}, {-1, -1}
#define C2_PK   0x4B0000004B000000ULL
#define NC2_PK  0xCB000000CB000000ULL
#define N1_PK   0xBF800000BF800000ULL

__device__ uint2 g_table[N_ATOMS * NNODES];   // ~12 MB scratch
__device__ int   g_start[N_GRAPHS + 1];

__device__ __forceinline__ float ex2f(float x) {
    float y; asm("ex2.approx.ftz.f32 %0, %1;" : "=f"(y) : "f"(x)); return y;
}
__device__ __forceinline__ uint32_t s2u(const void* p) {
    return (uint32_t)__cvta_generic_to_shared(p);
}
__device__ __forceinline__ void mbar_init(uint32_t a, uint32_t cnt) {
    asm volatile("mbarrier.init.shared.b64 [%0], %1;" :: "r"(a), "r"(cnt) : "memory");
}
__device__ __forceinline__ void mbar_expect_tx(uint32_t a, uint32_t tx) {
    asm volatile("mbarrier.arrive.expect_tx.shared.b64 _, [%0], %1;" :: "r"(a), "r"(tx) : "memory");
}
__device__ __forceinline__ void bulk_g2s(uint32_t dst, const void* src,
                                         uint32_t sz, uint32_t mbar) {
    asm volatile("cp.async.bulk.shared::cluster.global.mbarrier::complete_tx::bytes"
                 " [%0], [%1], %2, [%3];"
                 :: "r"(dst), "l"(src), "r"(sz), "r"(mbar) : "memory");
}
// Plain spin wait (R13 showed the sleep hint costs more than it saves here).
__device__ __forceinline__ void mbar_wait(uint32_t mbar, uint32_t phase) {
    asm volatile(
        "{\n\t"
        ".reg .pred P;\n\t"
        "WAIT_%=:\n\t"
        "mbarrier.try_wait.parity.acquire.cta.shared::cta.b64 P, [%0], %1;\n\t"
        "@P bra.uni DONE_%=;\n\t"
        "bra.uni WAIT_%=;\n\t"
        "DONE_%=:\n\t"
        "}" :: "r"(mbar), "r"(phase) : "memory");
}

// ---- packed f32x2 helpers (sm_100+ PTX-only ops) ----
__device__ __forceinline__ unsigned long long pack2(float lo, float hi) {
    unsigned long long d;
    asm("mov.b64 %0, {%1, %2};" : "=l"(d) : "f"(lo), "f"(hi));
    return d;
}
__device__ __forceinline__ void unpack2(unsigned long long v,
                                        uint32_t& lo, uint32_t& hi) {
    asm("mov.b64 {%0, %1}, %2;" : "=r"(lo), "=r"(hi) : "l"(v));
}
__device__ __forceinline__ unsigned long long addx2(unsigned long long a,
                                                    unsigned long long b) {
    unsigned long long d;
    asm("add.rn.f32x2 %0, %1, %2;" : "=l"(d) : "l"(a), "l"(b));
    return d;
}
__device__ __forceinline__ unsigned long long mulx2(unsigned long long a,
                                                    unsigned long long b) {
    unsigned long long d;
    asm("mul.rn.f32x2 %0, %1, %2;" : "=l"(d) : "l"(a), "l"(b));
    return d;
}
__device__ __forceinline__ unsigned long long fmax2(unsigned long long a,
                                                    unsigned long long b,
                                                    unsigned long long c) {
    unsigned long long d;
    asm("fma.rn.f32x2 %0, %1, %2, %3;" : "=l"(d) : "l"(a), "l"(b), "l"(c));
    return d;
}

// ---------------------------------------------------------------------------
// Build: per-atom fp16 Hermite-cubic table (geometric exp recurrence).
// Extra duties: zero the output array (blocks 0..2047); block 0 computes
// g_start[] from batch (dtype-detect + transition scan, disjoint writers).
__global__ __launch_bounds__(128)
void build_kernel(const float* __restrict__ coeff,
                  const int* __restrict__ braw,
                  float* __restrict__ out) {
    const int atom = blockIdx.x;
    const int tid  = threadIdx.x;
    __shared__ float w[N_GAUSS], wc[N_GAUSS], fstep[N_GAUSS];
    __shared__ float fv[NNODES + 1], mv[NNODES + 1];
    __shared__ int s_flag;

    // Zero output: 2048 blocks x 128 threads = 262144 = 64*4096 elements.
    if (atom < (N_GRAPHS * K_GRID) / 128)
        out[atom * 128 + tid] = 0.0f;

    // Block 0: compute g_start from batch.
    if (atom == 0) {
        if (tid == 0) s_flag = 0;
        __syncthreads();
        int loc = 0;
        for (int i = 1 + 2 * tid; i < N_ATOMS; i += 2 * 128) loc |= braw[i];
        if (loc) atomicOr(&s_flag, 1);
        __syncthreads();
        const bool is32 = (s_flag != 0);
        for (int i = tid; i < N_ATOMS; i += 128) {
            int bi = is32 ? braw[i] : braw[2 * i];
            int bp = (i == 0) ? -1 : (is32 ? braw[i - 1] : braw[2 * i - 2]);
            for (int gg = bp + 1; gg <= bi; gg++) g_start[gg] = i;
            if (i == N_ATOMS - 1)
                for (int gg = bi + 1; gg <= N_GRAPHS; gg++) g_start[gg] = N_ATOMS;
        }
    }

    if (tid < N_GAUSS) {
        int j = tid;
        float sigma = 0.5f + 0.3f * (float)j;
        float tt = sigma * 2.5066282746310002f;      // sigma*sqrt(2*pi)
        float sr = 1.0f / (tt * tt * tt);
        float cj = 1.0f / (sigma * sigma);
        float wj = coeff[atom * N_GAUSS + j] * sr;
        w[j]  = wj;
        wc[j] = wj * cj * (1.0f / TSCALE);           // df/dt = -sum wc*e
        float cL = 1.4426950408889634f * cj;
        fstep[j] = ex2f(-cL * (1.0f / TSCALE));
    }
    __syncthreads();

    {
        const int k0 = 4 * tid;                      // nodes k0..k0+3
        float s1[4] = {0.f, 0.f, 0.f, 0.f};
        float s2[4] = {0.f, 0.f, 0.f, 0.f};
        const float r20 = ((float)k0 - 0.5f) * (1.0f / TSCALE);
        #pragma unroll
        for (int j = 0; j < N_GAUSS; j++) {
            float sigma = 0.5f + 0.3f * (float)j;
            float cL = 1.4426950408889634f / (sigma * sigma);
            float e  = ex2f(-r20 * cL);
            const float f = fstep[j];
            const float wj = w[j], wcj = wc[j];
            #pragma unroll
            for (int m = 0; m < 4; m++) {
                s1[m] = fmaf(wj,  e, s1[m]);
                s2[m] = fmaf(wcj, e, s2[m]);
                e *= f;
            }
        }
        #pragma unroll
        for (int m = 0; m < 4; m++) { fv[k0 + m] = s1[m]; mv[k0 + m] = -s2[m]; }
    }
    if (tid == 0) {                                  // node 512 tail
        float r2 = 511.5f * (1.0f / TSCALE);
        float s1 = 0.f, s2 = 0.f;
        #pragma unroll
        for (int j = 0; j < N_GAUSS; j++) {
            float sigma = 0.5f + 0.3f * (float)j;
            float cL = 1.4426950408889634f / (sigma * sigma);
            float e = ex2f(-r2 * cL);
            s1 = fmaf(w[j],  e, s1);
            s2 = fmaf(wc[j], e, s2);
        }
        fv[NNODES] = s1; mv[NNODES] = -s2;
    }
    __syncthreads();

    for (int i = tid; i < NNODES; i += 128) {
        float fL = fv[i], fR = fv[i + 1];
        float mL = mv[i], mR = mv[i + 1];
        float dd = fR - fL;
        float a0 = fL, a1 = mL;
        float a2 = 3.0f * dd - 2.0f * mL - mR;
        float a3 = mL + mR - 2.0f * dd;
        // Shift Hermite basis v in [0,1] -> u = v-0.5 in [-0.5,0.5]:
        float c0 = a0 + 0.5f * a1 + 0.25f * a2 + 0.125f * a3;
        float c1 = a1 + a2 + 0.75f * a3;
        float c2 = a2 + 1.5f * a3;
        float c3 = a3;
        __half2 h01 = __floats2half2_rn(c0, c1);
        __half2 h23 = __floats2half2_rn(c2, c3);
        uint2 e;
        e.x = *reinterpret_cast<uint32_t*>(&h01);
        e.y = *reinterpret_cast<uint32_t*>(&h23);
        g_table[(size_t)atom * NNODES + i] = e;
    }
}

// ---------------------------------------------------------------------------
// Density: 1024 blocks (4 chunks x 64 graphs x 4 atom-splits), 256 threads,
// 4 points/thread processed as 2 packed f32x2 pairs. 4-atom fp16 tables per
// tile, double-buffered bulk copies.
__global__ __launch_bounds__(BLOCK, 6)
void density_kernel(const float* __restrict__ atom_coord,
                    const float* __restrict__ grid,
                    float* __restrict__ out) {
    extern __shared__ __align__(16) uint2 tbl[];    // [2][NTAB][NNODES]
    __shared__ float  sax[ACAP], say[ACAP], saz[ACAP];   // NEGATED scaled coords
    __shared__ __align__(8) unsigned long long mbar[2];

    const int g   = blockIdx.y;
    const int tid = threadIdx.x;
    const uint32_t mb0 = s2u(&mbar[0]);
    const uint32_t mb1 = s2u(&mbar[1]);

    if (tid == 0) {
        mbar_init(mb0, 1);
        mbar_init(mb1, 1);
        asm volatile("fence.proxy.async.shared::cta;" ::: "memory");
    }

    // Per-graph atom range (precomputed by build_kernel block 0).
    const int s0    = g_start[g];
    const int n_all = g_start[g + 1] - s0;
    const int part  = (n_all + ASPLIT - 1) / ASPLIT;
    const int aoff  = blockIdx.z * part;
    const int start = s0 + aoff;
    const int n     = min(n_all - aoff, part);

    const float S = 2.8284271247461903f;  // sqrt(8): t = |S*(p-a)|^2 = 8*r2
    const float* gp = grid + (size_t)g * K_GRID * 3;
    const int kb = blockIdx.x * CHUNK + tid;

    // Packed grid-point coords: pair p holds points q=2p, 2p+1.
    unsigned long long px2[NPAIR], py2[NPAIR], pz2[NPAIR];
    float acc[PPT];
    #pragma unroll
    for (int p = 0; p < NPAIR; p++) {
        const int kA = kb + (2 * p)     * BLOCK;
        const int kB = kb + (2 * p + 1) * BLOCK;
        px2[p] = pack2(gp[kA * 3 + 0] * S, gp[kB * 3 + 0] * S);
        py2[p] = pack2(gp[kA * 3 + 1] * S, gp[kB * 3 + 1] * S);
        pz2[p] = pack2(gp[kA * 3 + 2] * S, gp[kB * 3 + 2] * S);
    }
    #pragma unroll
    for (int q = 0; q < PPT; q++) acc[q] = 0.f;

    // Stage NEGATED scaled coords once (packed ADD then gives p - a).
    for (int a = tid; a < n; a += BLOCK) {
        const float* ac = atom_coord + (size_t)(start + a) * 3;
        sax[a] = -ac[0] * S;
        say[a] = -ac[1] * S;
        saz[a] = -ac[2] * S;
    }
    __syncthreads();   // coords + mbar init visible

    const int ntiles = (n + NTAB - 1) / NTAB;
    uint32_t ph0 = 0, ph1 = 0;

    // Prime tiles 0 and 1.
    if (tid == 0) {
        if (ntiles > 0) {
            uint32_t sz = (uint32_t)min(NTAB, n) * ABYTES;
            mbar_expect_tx(mb0, sz);
            bulk_g2s(s2u(tbl), g_table + (size_t)start * NNODES, sz, mb0);
        }
        if (ntiles > 1) {
            uint32_t sz = (uint32_t)min(NTAB, n - NTAB) * ABYTES;
            mbar_expect_tx(mb1, sz);
            bulk_g2s(s2u(tbl + NTAB * NNODES),
                     g_table + (size_t)(start + NTAB) * NNODES, sz, mb1);
        }
    }

    for (int s = 0; s < ntiles; s++) {
        const int buf = s & 1;
        if (buf == 0) { mbar_wait(mb0, ph0); ph0 ^= 1; }
        else          { mbar_wait(mb1, ph1); ph1 ^= 1; }

        const int a0  = s * NTAB;
        const int cnt = min(NTAB, n - a0);
        const char* tb0 = (const char*)(tbl + buf * (NTAB * NNODES));

        #pragma unroll
        for (int a = 0; a < NTAB; a++) {
            if (a < cnt) {
                const float nax = sax[a0 + a], nay = say[a0 + a], naz = saz[a0 + a];
                const unsigned long long nax2 = pack2(nax, nax);
                const unsigned long long nay2 = pack2(nay, nay);
                const unsigned long long naz2 = pack2(naz, naz);
                const char* tb = tb0 + a * ABYTES;
                #pragma unroll
                for (int p = 0; p < NPAIR; p++) {
                    unsigned long long dx2 = addx2(px2[p], nax2);
                    unsigned long long dy2 = addx2(py2[p], nay2);
                    unsigned long long dz2 = addx2(pz2[p], naz2);
                    unsigned long long t2  = fmax2(dx2, dx2,
                                             fmax2(dy2, dy2, mulx2(dz2, dz2)));
                    unsigned long long m2  = addx2(t2, C2_PK);   // round(t)+2^23
                    unsigned long long d2  = addx2(m2, NC2_PK);  // m-2^23 (exact)
                    unsigned long long u2  = fmax2(d2, N1_PK, t2); // t-d (exact)
                    uint32_t mb_[2], ub_[2];
                    unpack2(m2, mb_[0], mb_[1]);
                    unpack2(u2, ub_[0], ub_[1]);
                    #pragma unroll
                    for (int h = 0; h < 2; h++) {
                        int   i = min((int)(mb_[h] & 0x7FFFFF), NNODES - 1);
                        float u = __uint_as_float(ub_[h]);
                        uint2 e = *reinterpret_cast<const uint2*>(tb + i * 8);
                        float2 c01 = __half22float2(*reinterpret_cast<__half2*>(&e.x));
                        float2 c23 = __half22float2(*reinterpret_cast<__half2*>(&e.y));
                        acc[2 * p + h] +=
                            fmaf(fmaf(fmaf(c23.y, u, c23.x), u, c01.y), u, c01.x);
                    }
                }
            }
        }

        __syncthreads();   // all reads of tbl[buf] done before restage
        if (tid == 0 && s + 2 < ntiles) {
            const int an = (s + 2) * NTAB;
            uint32_t sz = (uint32_t)min(NTAB, n - an) * ABYTES;
            uint32_t mb = buf ? mb1 : mb0;
            mbar_expect_tx(mb, sz);
            bulk_g2s(s2u(tbl + buf * (NTAB * NNODES)),
                     g_table + (size_t)(start + an) * NNODES, sz, mb);
        }
    }

    float* op = out + (size_t)g * K_GRID;
    #pragma unroll
    for (int q = 0; q < PPT; q++)
        atomicAdd(&op[kb + q * BLOCK], acc[q]);
}

// ---------------------------------------------------------------------------
extern "C" void kernel_launch(void* const* d_in, const int* in_sizes, int n_in,
                              void* d_out, int out_size) {
    const float* coeff      = (const float*)d_in[0];
    const float* atom_coord = (const float*)d_in[1];
    const float* grid       = (const float*)d_in[2];
    const int*   batch_raw  = (const int*)d_in[3];
    float* out = (float*)d_out;

    static bool attr_done = false;
    if (!attr_done) {
        cudaFuncSetAttribute(density_kernel,
                             cudaFuncAttributeMaxDynamicSharedMemorySize,
                             SMEM_DYN);
        attr_done = true;
    }

    build_kernel<<<N_ATOMS, 128>>>(coeff, batch_raw, out);
    density_kernel<<<dim3(NCHUNK, N_GRAPHS, ASPLIT), BLOCK, SMEM_DYN>>>(
        atom_coord, grid, out);
}

// round 15
// speedup vs baseline: 1.0251x; 1.0091x over previous
#include <cuda_runtime.h>
#include <cuda_fp16.h>
#include <cstdint>

#define N_GAUSS   16
#define N_ATOMS   3072
#define N_GRAPHS  64
#define K_GRID    4096

// Table: per atom, 512 cubic intervals over t = 8*r2. Interval i = round(t)
// covers t in [i-0.5, i+0.5]; local parameter u = t - i in [-0.5, 0.5].
// Entry = 4 coefficients quantized to fp16, packed in uint2 (8 bytes).
#define NNODES    512
#define TSCALE    8.0f
#define ABYTES    (NNODES * 8)      // 4 KB per atom table

#define BLOCK     256
#define PPT       4
#define NPAIR     (PPT/2)
#define CHUNK     (BLOCK*PPT)       // 1024
#define NCHUNK    (K_GRID/CHUNK)    // 4
#define ASPLIT    4                 // -> 1024 blocks

#define NTAB      4                 // atoms per tile buffer
#define SMEM_DYN  (2 * NTAB * ABYTES)   // 32 KB (double buffer)
#define ACAP      128

// Packed f32x2 constants: {2^23, 2^23}, {-2^23, -2^23}, {-1, -1}
#define C2_PK   0x4B0000004B000000ULL
#define NC2_PK  0xCB000000CB000000ULL
#define N1_PK   0xBF800000BF800000ULL

__device__ uint2 g_table[N_ATOMS * NNODES];   // ~12 MB scratch
__device__ int   g_start[N_GRAPHS + 1];

__device__ __forceinline__ float ex2f(float x) {
    float y; asm("ex2.approx.ftz.f32 %0, %1;" : "=f"(y) : "f"(x)); return y;
}
__device__ __forceinline__ uint32_t s2u(const void* p) {
    return (uint32_t)__cvta_generic_to_shared(p);
}
__device__ __forceinline__ void mbar_init(uint32_t a, uint32_t cnt) {
    asm volatile("mbarrier.init.shared.b64 [%0], %1;" :: "r"(a), "r"(cnt) : "memory");
}
__device__ __forceinline__ void mbar_expect_tx(uint32_t a, uint32_t tx) {
    asm volatile("mbarrier.arrive.expect_tx.shared.b64 _, [%0], %1;" :: "r"(a), "r"(tx) : "memory");
}
__device__ __forceinline__ void bulk_g2s(uint32_t dst, const void* src,
                                         uint32_t sz, uint32_t mbar) {
    asm volatile("cp.async.bulk.shared::cluster.global.mbarrier::complete_tx::bytes"
                 " [%0], [%1], %2, [%3];"
                 :: "r"(dst), "l"(src), "r"(sz), "r"(mbar) : "memory");
}
// Plain spin wait (R13: sleep hint costs more than it saves here).
__device__ __forceinline__ void mbar_wait(uint32_t mbar, uint32_t phase) {
    asm volatile(
        "{\n\t"
        ".reg .pred P;\n\t"
        "WAIT_%=:\n\t"
        "mbarrier.try_wait.parity.acquire.cta.shared::cta.b64 P, [%0], %1;\n\t"
        "@P bra.uni DONE_%=;\n\t"
        "bra.uni WAIT_%=;\n\t"
        "DONE_%=:\n\t"
        "}" :: "r"(mbar), "r"(phase) : "memory");
}

// ---- packed f32x2 helpers (sm_100+ PTX-only ops) ----
__device__ __forceinline__ unsigned long long pack2(float lo, float hi) {
    unsigned long long d;
    asm("mov.b64 %0, {%1, %2};" : "=l"(d) : "f"(lo), "f"(hi));
    return d;
}
__device__ __forceinline__ void unpack2(unsigned long long v,
                                        uint32_t& lo, uint32_t& hi) {
    asm("mov.b64 {%0, %1}, %2;" : "=r"(lo), "=r"(hi) : "l"(v));
}
__device__ __forceinline__ unsigned long long addx2(unsigned long long a,
                                                    unsigned long long b) {
    unsigned long long d;
    asm("add.rn.f32x2 %0, %1, %2;" : "=l"(d) : "l"(a), "l"(b));
    return d;
}
__device__ __forceinline__ unsigned long long mulx2(unsigned long long a,
                                                    unsigned long long b) {
    unsigned long long d;
    asm("mul.rn.f32x2 %0, %1, %2;" : "=l"(d) : "l"(a), "l"(b));
    return d;
}
__device__ __forceinline__ unsigned long long fmax2(unsigned long long a,
                                                    unsigned long long b,
                                                    unsigned long long c) {
    unsigned long long d;
    asm("fma.rn.f32x2 %0, %1, %2, %3;" : "=l"(d) : "l"(a), "l"(b), "l"(c));
    return d;
}

// ---------------------------------------------------------------------------
// Build: per-atom fp16 Hermite-cubic table (geometric exp recurrence).
// Extra duties: zero the output array (blocks 0..2047); block 0 computes
// g_start[] from batch (dtype-detect + transition scan, disjoint writers).
__global__ __launch_bounds__(128)
void build_kernel(const float* __restrict__ coeff,
                  const int* __restrict__ braw,
                  float* __restrict__ out) {
    const int atom = blockIdx.x;
    const int tid  = threadIdx.x;
    __shared__ float w[N_GAUSS], wc[N_GAUSS], fstep[N_GAUSS];
    __shared__ float fv[NNODES + 1], mv[NNODES + 1];
    __shared__ int s_flag;

    // Zero output: 2048 blocks x 128 threads = 262144 = 64*4096 elements.
    if (atom < (N_GRAPHS * K_GRID) / 128)
        out[atom * 128 + tid] = 0.0f;

    // Block 0: compute g_start from batch.
    if (atom == 0) {
        if (tid == 0) s_flag = 0;
        __syncthreads();
        int loc = 0;
        for (int i = 1 + 2 * tid; i < N_ATOMS; i += 2 * 128) loc |= braw[i];
        if (loc) atomicOr(&s_flag, 1);
        __syncthreads();
        const bool is32 = (s_flag != 0);
        for (int i = tid; i < N_ATOMS; i += 128) {
            int bi = is32 ? braw[i] : braw[2 * i];
            int bp = (i == 0) ? -1 : (is32 ? braw[i - 1] : braw[2 * i - 2]);
            for (int gg = bp + 1; gg <= bi; gg++) g_start[gg] = i;
            if (i == N_ATOMS - 1)
                for (int gg = bi + 1; gg <= N_GRAPHS; gg++) g_start[gg] = N_ATOMS;
        }
    }

    if (tid < N_GAUSS) {
        int j = tid;
        float sigma = 0.5f + 0.3f * (float)j;
        float tt = sigma * 2.5066282746310002f;      // sigma*sqrt(2*pi)
        float sr = 1.0f / (tt * tt * tt);
        float cj = 1.0f / (sigma * sigma);
        float wj = coeff[atom * N_GAUSS + j] * sr;
        w[j]  = wj;
        wc[j] = wj * cj * (1.0f / TSCALE);           // df/dt = -sum wc*e
        float cL = 1.4426950408889634f * cj;
        fstep[j] = ex2f(-cL * (1.0f / TSCALE));
    }
    __syncthreads();

    {
        const int k0 = 4 * tid;                      // nodes k0..k0+3
        float s1[4] = {0.f, 0.f, 0.f, 0.f};
        float s2[4] = {0.f, 0.f, 0.f, 0.f};
        const float r20 = ((float)k0 - 0.5f) * (1.0f / TSCALE);
        #pragma unroll
        for (int j = 0; j < N_GAUSS; j++) {
            float sigma = 0.5f + 0.3f * (float)j;
            float cL = 1.4426950408889634f / (sigma * sigma);
            float e  = ex2f(-r20 * cL);
            const float f = fstep[j];
            const float wj = w[j], wcj = wc[j];
            #pragma unroll
            for (int m = 0; m < 4; m++) {
                s1[m] = fmaf(wj,  e, s1[m]);
                s2[m] = fmaf(wcj, e, s2[m]);
                e *= f;
            }
        }
        #pragma unroll
        for (int m = 0; m < 4; m++) { fv[k0 + m] = s1[m]; mv[k0 + m] = -s2[m]; }
    }
    if (tid == 0) {                                  // node 512 tail
        float r2 = 511.5f * (1.0f / TSCALE);
        float s1 = 0.f, s2 = 0.f;
        #pragma unroll
        for (int j = 0; j < N_GAUSS; j++) {
            float sigma = 0.5f + 0.3f * (float)j;
            float cL = 1.4426950408889634f / (sigma * sigma);
            float e = ex2f(-r2 * cL);
            s1 = fmaf(w[j],  e, s1);
            s2 = fmaf(wc[j], e, s2);
        }
        fv[NNODES] = s1; mv[NNODES] = -s2;
    }
    __syncthreads();

    for (int i = tid; i < NNODES; i += 128) {
        float fL = fv[i], fR = fv[i + 1];
        float mL = mv[i], mR = mv[i + 1];
        float dd = fR - fL;
        float a0 = fL, a1 = mL;
        float a2 = 3.0f * dd - 2.0f * mL - mR;
        float a3 = mL + mR - 2.0f * dd;
        // Shift Hermite basis v in [0,1] -> u = v-0.5 in [-0.5,0.5]:
        float c0 = a0 + 0.5f * a1 + 0.25f * a2 + 0.125f * a3;
        float c1 = a1 + a2 + 0.75f * a3;
        float c2 = a2 + 1.5f * a3;
        float c3 = a3;
        __half2 h01 = __floats2half2_rn(c0, c1);
        __half2 h23 = __floats2half2_rn(c2, c3);
        uint2 e;
        e.x = *reinterpret_cast<uint32_t*>(&h01);
        e.y = *reinterpret_cast<uint32_t*>(&h23);
        g_table[(size_t)atom * NNODES + i] = e;
    }
}

// ---------------------------------------------------------------------------
// Density: 1024 blocks (4 chunks x 64 graphs x 4 atom-splits), 256 threads,
// 4 points/thread as 2 packed f32x2 pairs. 4-atom fp16 tables per tile,
// double-buffered bulk copies. Full tiles take a branch-free unrolled path.
struct EvalState {
    unsigned long long px2[NPAIR], py2[NPAIR], pz2[NPAIR];
    float acc[PPT];
};

__device__ __forceinline__ void eval_atom(
    EvalState& st, const unsigned long long* __restrict__ csm, int aidx,
    const char* __restrict__ tb)
{
    const unsigned long long nax2 = csm[3 * aidx + 0];   // {-S*ax, -S*ax}
    const unsigned long long nay2 = csm[3 * aidx + 1];
    const unsigned long long naz2 = csm[3 * aidx + 2];
    #pragma unroll
    for (int p = 0; p < NPAIR; p++) {
        unsigned long long dx2 = addx2(st.px2[p], nax2);
        unsigned long long dy2 = addx2(st.py2[p], nay2);
        unsigned long long dz2 = addx2(st.pz2[p], naz2);
        unsigned long long t2  = fmax2(dx2, dx2, fmax2(dy2, dy2, mulx2(dz2, dz2)));
        unsigned long long m2  = addx2(t2, C2_PK);     // round(t)+2^23
        unsigned long long d2  = addx2(m2, NC2_PK);    // m-2^23 (exact)
        unsigned long long u2  = fmax2(d2, N1_PK, t2); // t-d (exact)
        uint32_t mb_[2], ub_[2];
        unpack2(m2, mb_[0], mb_[1]);
        unpack2(u2, ub_[0], ub_[1]);
        #pragma unroll
        for (int h = 0; h < 2; h++) {
            int   i = min((int)(mb_[h] & 0x7FFFFF), NNODES - 1);
            float u = __uint_as_float(ub_[h]);
            uint2 e = *reinterpret_cast<const uint2*>(tb + i * 8);
            float2 c01 = __half22float2(*reinterpret_cast<__half2*>(&e.x));
            float2 c23 = __half22float2(*reinterpret_cast<__half2*>(&e.y));
            st.acc[2 * p + h] +=
                fmaf(fmaf(fmaf(c23.y, u, c23.x), u, c01.y), u, c01.x);
        }
    }
}

__global__ __launch_bounds__(BLOCK, 6)
void density_kernel(const float* __restrict__ atom_coord,
                    const float* __restrict__ grid,
                    float* __restrict__ out) {
    extern __shared__ __align__(16) uint2 tbl[];    // [2][NTAB][NNODES]
    __shared__ unsigned long long csm[3 * ACAP];    // packed {-S*a,-S*a} coords
    __shared__ __align__(8) unsigned long long mbar[2];

    const int g   = blockIdx.y;
    const int tid = threadIdx.x;
    const uint32_t mb0 = s2u(&mbar[0]);
    const uint32_t mb1 = s2u(&mbar[1]);

    if (tid == 0) {
        mbar_init(mb0, 1);
        mbar_init(mb1, 1);
        asm volatile("fence.proxy.async.shared::cta;" ::: "memory");
    }

    // Per-graph atom range (precomputed by build_kernel block 0).
    const int s0    = g_start[g];
    const int n_all = g_start[g + 1] - s0;
    const int part  = (n_all + ASPLIT - 1) / ASPLIT;
    const int aoff  = blockIdx.z * part;
    const int start = s0 + aoff;
    const int n     = min(n_all - aoff, part);

    const float S = 2.8284271247461903f;  // sqrt(8): t = |S*(p-a)|^2 = 8*r2
    const float* gp = grid + (size_t)g * K_GRID * 3;
    const int kb = blockIdx.x * CHUNK + tid;

    EvalState st;
    #pragma unroll
    for (int p = 0; p < NPAIR; p++) {
        const int kA = kb + (2 * p)     * BLOCK;
        const int kB = kb + (2 * p + 1) * BLOCK;
        st.px2[p] = pack2(gp[kA * 3 + 0] * S, gp[kB * 3 + 0] * S);
        st.py2[p] = pack2(gp[kA * 3 + 1] * S, gp[kB * 3 + 1] * S);
        st.pz2[p] = pack2(gp[kA * 3 + 2] * S, gp[kB * 3 + 2] * S);
    }
    #pragma unroll
    for (int q = 0; q < PPT; q++) st.acc[q] = 0.f;

    // Stage negated, scaled, pair-duplicated coords once.
    for (int a = tid; a < n; a += BLOCK) {
        const float* ac = atom_coord + (size_t)(start + a) * 3;
        float vx = -ac[0] * S, vy = -ac[1] * S, vz = -ac[2] * S;
        csm[3 * a + 0] = pack2(vx, vx);
        csm[3 * a + 1] = pack2(vy, vy);
        csm[3 * a + 2] = pack2(vz, vz);
    }
    __syncthreads();   // coords + mbar init visible

    const int ntiles = (n + NTAB - 1) / NTAB;
    uint32_t ph0 = 0, ph1 = 0;

    // Prime tiles 0 and 1.
    if (tid == 0) {
        if (ntiles > 0) {
            uint32_t sz = (uint32_t)min(NTAB, n) * ABYTES;
            mbar_expect_tx(mb0, sz);
            bulk_g2s(s2u(tbl), g_table + (size_t)start * NNODES, sz, mb0);
        }
        if (ntiles > 1) {
            uint32_t sz = (uint32_t)min(NTAB, n - NTAB) * ABYTES;
            mbar_expect_tx(mb1, sz);
            bulk_g2s(s2u(tbl + NTAB * NNODES),
                     g_table + (size_t)(start + NTAB) * NNODES, sz, mb1);
        }
    }

    for (int s = 0; s < ntiles; s++) {
        const int buf = s & 1;
        if (buf == 0) { mbar_wait(mb0, ph0); ph0 ^= 1; }
        else          { mbar_wait(mb1, ph1); ph1 ^= 1; }

        const int a0  = s * NTAB;
        const int cnt = min(NTAB, n - a0);
        const char* tb0 = (const char*)(tbl + buf * (NTAB * NNODES));

        if (cnt == NTAB) {
            // Branch-free straight-line path (the common case).
            #pragma unroll
            for (int a = 0; a < NTAB; a++)
                eval_atom(st, csm, a0 + a, tb0 + a * ABYTES);
        } else {
            for (int a = 0; a < cnt; a++)
                eval_atom(st, csm, a0 + a, tb0 + a * ABYTES);
        }

        __syncthreads();   // all reads of tbl[buf] done before restage
        if (tid == 0 && s + 2 < ntiles) {
            const int an = (s + 2) * NTAB;
            uint32_t sz = (uint32_t)min(NTAB, n - an) * ABYTES;
            uint32_t mb = buf ? mb1 : mb0;
            mbar_expect_tx(mb, sz);
            bulk_g2s(s2u(tbl + buf * (NTAB * NNODES)),
                     g_table + (size_t)(start + an) * NNODES, sz, mb);
        }
    }

    float* op = out + (size_t)g * K_GRID;
    #pragma unroll
    for (int q = 0; q < PPT; q++)
        atomicAdd(&op[kb + q * BLOCK], st.acc[q]);
}

// ---------------------------------------------------------------------------
extern "C" void kernel_launch(void* const* d_in, const int* in_sizes, int n_in,
                              void* d_out, int out_size) {
    const float* coeff      = (const float*)d_in[0];
    const float* atom_coord = (const float*)d_in[1];
    const float* grid       = (const float*)d_in[2];
    const int*   batch_raw  = (const int*)d_in[3];
    float* out = (float*)d_out;

    static bool attr_done = false;
    if (!attr_done) {
        cudaFuncSetAttribute(density_kernel,
                             cudaFuncAttributeMaxDynamicSharedMemorySize,
                             SMEM_DYN);
        attr_done = true;
    }

    build_kernel<<<N_ATOMS, 128>>>(coeff, batch_raw, out);
    density_kernel<<<dim3(NCHUNK, N_GRAPHS, ASPLIT), BLOCK, SMEM_DYN>>>(
        atom_coord, grid, out);
}

// round 16
// speedup vs baseline: 1.0614x; 1.0354x over previous
#include <cuda_runtime.h>
#include <cuda_fp16.h>
#include <cstdint>

#define N_GAUSS   16
#define N_ATOMS   3072
#define N_GRAPHS  64
#define K_GRID    4096

// Table: per atom, 512 cubic intervals over t = 8*r2. Interval i = round(t)
// covers t in [i-0.5, i+0.5]; local parameter u = t - i in [-0.5, 0.5].
// Entry = 4 coefficients quantized to fp16, packed in uint2 (8 bytes).
#define NNODES    512
#define TSCALE    8.0f
#define ABYTES    (NNODES * 8)      // 4 KB per atom table

#define BLOCK     256
#define PPT       4
#define NPAIR     (PPT/2)
#define CHUNK     (BLOCK*PPT)       // 1024
#define NCHUNK    (K_GRID/CHUNK)    // 4
#define ASPLIT    3                 // -> 768 blocks = ONE wave at 6 blocks/SM

#define NTAB      4                 // atoms per tile buffer
#define SMEM_DYN  (2 * NTAB * ABYTES)   // 32 KB (double buffer)
#define ACAP      128

// Packed f32x2 constants: {2^23, 2^23}, {-2^23, -2^23}, {-1, -1}
#define C2_PK   0x4B0000004B000000ULL
#define NC2_PK  0xCB000000CB000000ULL
#define N1_PK   0xBF800000BF800000ULL

__device__ uint2 g_table[N_ATOMS * NNODES];   // ~12 MB scratch
__device__ int   g_start[N_GRAPHS + 1];

__device__ __forceinline__ float ex2f(float x) {
    float y; asm("ex2.approx.ftz.f32 %0, %1;" : "=f"(y) : "f"(x)); return y;
}
__device__ __forceinline__ uint32_t s2u(const void* p) {
    return (uint32_t)__cvta_generic_to_shared(p);
}
__device__ __forceinline__ void mbar_init(uint32_t a, uint32_t cnt) {
    asm volatile("mbarrier.init.shared.b64 [%0], %1;" :: "r"(a), "r"(cnt) : "memory");
}
__device__ __forceinline__ void mbar_expect_tx(uint32_t a, uint32_t tx) {
    asm volatile("mbarrier.arrive.expect_tx.shared.b64 _, [%0], %1;" :: "r"(a), "r"(tx) : "memory");
}
__device__ __forceinline__ void bulk_g2s(uint32_t dst, const void* src,
                                         uint32_t sz, uint32_t mbar) {
    asm volatile("cp.async.bulk.shared::cluster.global.mbarrier::complete_tx::bytes"
                 " [%0], [%1], %2, [%3];"
                 :: "r"(dst), "l"(src), "r"(sz), "r"(mbar) : "memory");
}
// Plain spin wait (R13: sleep hint costs more than it saves here).
__device__ __forceinline__ void mbar_wait(uint32_t mbar, uint32_t phase) {
    asm volatile(
        "{\n\t"
        ".reg .pred P;\n\t"
        "WAIT_%=:\n\t"
        "mbarrier.try_wait.parity.acquire.cta.shared::cta.b64 P, [%0], %1;\n\t"
        "@P bra.uni DONE_%=;\n\t"
        "bra.uni WAIT_%=;\n\t"
        "DONE_%=:\n\t"
        "}" :: "r"(mbar), "r"(phase) : "memory");
}

// ---- packed f32x2 helpers (sm_100+ PTX-only ops) ----
__device__ __forceinline__ unsigned long long pack2(float lo, float hi) {
    unsigned long long d;
    asm("mov.b64 %0, {%1, %2};" : "=l"(d) : "f"(lo), "f"(hi));
    return d;
}
__device__ __forceinline__ void unpack2(unsigned long long v,
                                        uint32_t& lo, uint32_t& hi) {
    asm("mov.b64 {%0, %1}, %2;" : "=r"(lo), "=r"(hi) : "l"(v));
}
__device__ __forceinline__ unsigned long long addx2(unsigned long long a,
                                                    unsigned long long b) {
    unsigned long long d;
    asm("add.rn.f32x2 %0, %1, %2;" : "=l"(d) : "l"(a), "l"(b));
    return d;
}
__device__ __forceinline__ unsigned long long mulx2(unsigned long long a,
                                                    unsigned long long b) {
    unsigned long long d;
    asm("mul.rn.f32x2 %0, %1, %2;" : "=l"(d) : "l"(a), "l"(b));
    return d;
}
__device__ __forceinline__ unsigned long long fmax2(unsigned long long a,
                                                    unsigned long long b,
                                                    unsigned long long c) {
    unsigned long long d;
    asm("fma.rn.f32x2 %0, %1, %2, %3;" : "=l"(d) : "l"(a), "l"(b), "l"(c));
    return d;
}

// ---------------------------------------------------------------------------
// Build: per-atom fp16 Hermite-cubic table (geometric exp recurrence).
// Extra duties: zero the output array (blocks 0..2047); block 0 computes
// g_start[] from batch (dtype-detect + transition scan, disjoint writers).
__global__ __launch_bounds__(128)
void build_kernel(const float* __restrict__ coeff,
                  const int* __restrict__ braw,
                  float* __restrict__ out) {
    const int atom = blockIdx.x;
    const int tid  = threadIdx.x;
    __shared__ float w[N_GAUSS], wc[N_GAUSS], fstep[N_GAUSS];
    __shared__ float fv[NNODES + 1], mv[NNODES + 1];
    __shared__ int s_flag;

    // Zero output: 2048 blocks x 128 threads = 262144 = 64*4096 elements.
    if (atom < (N_GRAPHS * K_GRID) / 128)
        out[atom * 128 + tid] = 0.0f;

    // Block 0: compute g_start from batch.
    if (atom == 0) {
        if (tid == 0) s_flag = 0;
        __syncthreads();
        int loc = 0;
        for (int i = 1 + 2 * tid; i < N_ATOMS; i += 2 * 128) loc |= braw[i];
        if (loc) atomicOr(&s_flag, 1);
        __syncthreads();
        const bool is32 = (s_flag != 0);
        for (int i = tid; i < N_ATOMS; i += 128) {
            int bi = is32 ? braw[i] : braw[2 * i];
            int bp = (i == 0) ? -1 : (is32 ? braw[i - 1] : braw[2 * i - 2]);
            for (int gg = bp + 1; gg <= bi; gg++) g_start[gg] = i;
            if (i == N_ATOMS - 1)
                for (int gg = bi + 1; gg <= N_GRAPHS; gg++) g_start[gg] = N_ATOMS;
        }
    }

    if (tid < N_GAUSS) {
        int j = tid;
        float sigma = 0.5f + 0.3f * (float)j;
        float tt = sigma * 2.5066282746310002f;      // sigma*sqrt(2*pi)
        float sr = 1.0f / (tt * tt * tt);
        float cj = 1.0f / (sigma * sigma);
        float wj = coeff[atom * N_GAUSS + j] * sr;
        w[j]  = wj;
        wc[j] = wj * cj * (1.0f / TSCALE);           // df/dt = -sum wc*e
        float cL = 1.4426950408889634f * cj;
        fstep[j] = ex2f(-cL * (1.0f / TSCALE));
    }
    __syncthreads();

    {
        const int k0 = 4 * tid;                      // nodes k0..k0+3
        float s1[4] = {0.f, 0.f, 0.f, 0.f};
        float s2[4] = {0.f, 0.f, 0.f, 0.f};
        const float r20 = ((float)k0 - 0.5f) * (1.0f / TSCALE);
        #pragma unroll
        for (int j = 0; j < N_GAUSS; j++) {
            float sigma = 0.5f + 0.3f * (float)j;
            float cL = 1.4426950408889634f / (sigma * sigma);
            float e  = ex2f(-r20 * cL);
            const float f = fstep[j];
            const float wj = w[j], wcj = wc[j];
            #pragma unroll
            for (int m = 0; m < 4; m++) {
                s1[m] = fmaf(wj,  e, s1[m]);
                s2[m] = fmaf(wcj, e, s2[m]);
                e *= f;
            }
        }
        #pragma unroll
        for (int m = 0; m < 4; m++) { fv[k0 + m] = s1[m]; mv[k0 + m] = -s2[m]; }
    }
    if (tid == 0) {                                  // node 512 tail
        float r2 = 511.5f * (1.0f / TSCALE);
        float s1 = 0.f, s2 = 0.f;
        #pragma unroll
        for (int j = 0; j < N_GAUSS; j++) {
            float sigma = 0.5f + 0.3f * (float)j;
            float cL = 1.4426950408889634f / (sigma * sigma);
            float e = ex2f(-r2 * cL);
            s1 = fmaf(w[j],  e, s1);
            s2 = fmaf(wc[j], e, s2);
        }
        fv[NNODES] = s1; mv[NNODES] = -s2;
    }
    __syncthreads();

    for (int i = tid; i < NNODES; i += 128) {
        float fL = fv[i], fR = fv[i + 1];
        float mL = mv[i], mR = mv[i + 1];
        float dd = fR - fL;
        float a0 = fL, a1 = mL;
        float a2 = 3.0f * dd - 2.0f * mL - mR;
        float a3 = mL + mR - 2.0f * dd;
        // Shift Hermite basis v in [0,1] -> u = v-0.5 in [-0.5,0.5]:
        float c0 = a0 + 0.5f * a1 + 0.25f * a2 + 0.125f * a3;
        float c1 = a1 + a2 + 0.75f * a3;
        float c2 = a2 + 1.5f * a3;
        float c3 = a3;
        __half2 h01 = __floats2half2_rn(c0, c1);
        __half2 h23 = __floats2half2_rn(c2, c3);
        uint2 e;
        e.x = *reinterpret_cast<uint32_t*>(&h01);
        e.y = *reinterpret_cast<uint32_t*>(&h23);
        g_table[(size_t)atom * NNODES + i] = e;
    }
}

// ---------------------------------------------------------------------------
// Density: 768 blocks (4 chunks x 64 graphs x 3 atom-splits), 256 threads,
// 4 points/thread as 2 packed f32x2 pairs. 4-atom fp16 tables per tile,
// double-buffered bulk copies. Single wave at 6 blocks/SM.
struct EvalState {
    unsigned long long px2[NPAIR], py2[NPAIR], pz2[NPAIR];
    float acc[PPT];
};

__device__ __forceinline__ void eval_atom(
    EvalState& st, float nax, float nay, float naz,
    const char* __restrict__ tb)
{
    const unsigned long long nax2 = pack2(nax, nax);
    const unsigned long long nay2 = pack2(nay, nay);
    const unsigned long long naz2 = pack2(naz, naz);
    #pragma unroll
    for (int p = 0; p < NPAIR; p++) {
        unsigned long long dx2 = addx2(st.px2[p], nax2);
        unsigned long long dy2 = addx2(st.py2[p], nay2);
        unsigned long long dz2 = addx2(st.pz2[p], naz2);
        unsigned long long t2  = fmax2(dx2, dx2, fmax2(dy2, dy2, mulx2(dz2, dz2)));
        unsigned long long m2  = addx2(t2, C2_PK);     // round(t)+2^23
        unsigned long long d2  = addx2(m2, NC2_PK);    // m-2^23 (exact)
        unsigned long long u2  = fmax2(d2, N1_PK, t2); // t-d (exact)
        uint32_t mb_[2], ub_[2];
        unpack2(m2, mb_[0], mb_[1]);
        unpack2(u2, ub_[0], ub_[1]);
        #pragma unroll
        for (int h = 0; h < 2; h++) {
            int   i = min((int)(mb_[h] & 0x7FFFFF), NNODES - 1);
            float u = __uint_as_float(ub_[h]);
            uint2 e = *reinterpret_cast<const uint2*>(tb + i * 8);
            float2 c01 = __half22float2(*reinterpret_cast<__half2*>(&e.x));
            float2 c23 = __half22float2(*reinterpret_cast<__half2*>(&e.y));
            st.acc[2 * p + h] +=
                fmaf(fmaf(fmaf(c23.y, u, c23.x), u, c01.y), u, c01.x);
        }
    }
}

__global__ __launch_bounds__(BLOCK, 6)
void density_kernel(const float* __restrict__ atom_coord,
                    const float* __restrict__ grid,
                    float* __restrict__ out) {
    extern __shared__ __align__(16) uint2 tbl[];    // [2][NTAB][NNODES]
    __shared__ float sax[ACAP], say[ACAP], saz[ACAP];   // negated scaled coords
    __shared__ __align__(8) unsigned long long mbar[2];

    const int g   = blockIdx.y;
    const int tid = threadIdx.x;
    const uint32_t mb0 = s2u(&mbar[0]);
    const uint32_t mb1 = s2u(&mbar[1]);

    if (tid == 0) {
        mbar_init(mb0, 1);
        mbar_init(mb1, 1);
        asm volatile("fence.proxy.async.shared::cta;" ::: "memory");
    }

    // Per-graph atom range (precomputed by build_kernel block 0).
    const int s0    = g_start[g];
    const int n_all = g_start[g + 1] - s0;
    const int part  = (n_all + ASPLIT - 1) / ASPLIT;
    const int aoff  = blockIdx.z * part;
    const int start = s0 + aoff;
    const int n     = min(n_all - aoff, part);

    const float S = 2.8284271247461903f;  // sqrt(8): t = |S*(p-a)|^2 = 8*r2
    const float* gp = grid + (size_t)g * K_GRID * 3;
    const int kb = blockIdx.x * CHUNK + tid;

    EvalState st;
    #pragma unroll
    for (int p = 0; p < NPAIR; p++) {
        const int kA = kb + (2 * p)     * BLOCK;
        const int kB = kb + (2 * p + 1) * BLOCK;
        st.px2[p] = pack2(gp[kA * 3 + 0] * S, gp[kB * 3 + 0] * S);
        st.py2[p] = pack2(gp[kA * 3 + 1] * S, gp[kB * 3 + 1] * S);
        st.pz2[p] = pack2(gp[kA * 3 + 2] * S, gp[kB * 3 + 2] * S);
    }
    #pragma unroll
    for (int q = 0; q < PPT; q++) st.acc[q] = 0.f;

    // Stage negated, scaled coords once.
    for (int a = tid; a < n; a += BLOCK) {
        const float* ac = atom_coord + (size_t)(start + a) * 3;
        sax[a] = -ac[0] * S;
        say[a] = -ac[1] * S;
        saz[a] = -ac[2] * S;
    }
    __syncthreads();   // coords + mbar init visible

    const int ntiles = (n + NTAB - 1) / NTAB;
    uint32_t ph0 = 0, ph1 = 0;

    // Prime tiles 0 and 1.
    if (tid == 0) {
        if (ntiles > 0) {
            uint32_t sz = (uint32_t)min(NTAB, n) * ABYTES;
            mbar_expect_tx(mb0, sz);
            bulk_g2s(s2u(tbl), g_table + (size_t)start * NNODES, sz, mb0);
        }
        if (ntiles > 1) {
            uint32_t sz = (uint32_t)min(NTAB, n - NTAB) * ABYTES;
            mbar_expect_tx(mb1, sz);
            bulk_g2s(s2u(tbl + NTAB * NNODES),
                     g_table + (size_t)(start + NTAB) * NNODES, sz, mb1);
        }
    }

    for (int s = 0; s < ntiles; s++) {
        const int buf = s & 1;
        if (buf == 0) { mbar_wait(mb0, ph0); ph0 ^= 1; }
        else          { mbar_wait(mb1, ph1); ph1 ^= 1; }

        const int a0  = s * NTAB;
        const int cnt = min(NTAB, n - a0);
        const char* tb0 = (const char*)(tbl + buf * (NTAB * NNODES));

        if (cnt == NTAB) {
            // Branch-free straight-line path (the common case).
            #pragma unroll
            for (int a = 0; a < NTAB; a++)
                eval_atom(st, sax[a0 + a], say[a0 + a], saz[a0 + a],
                          tb0 + a * ABYTES);
        } else {
            for (int a = 0; a < cnt; a++)
                eval_atom(st, sax[a0 + a], say[a0 + a], saz[a0 + a],
                          tb0 + a * ABYTES);
        }

        __syncthreads();   // all reads of tbl[buf] done before restage
        if (tid == 0 && s + 2 < ntiles) {
            const int an = (s + 2) * NTAB;
            uint32_t sz = (uint32_t)min(NTAB, n - an) * ABYTES;
            uint32_t mb = buf ? mb1 : mb0;
            mbar_expect_tx(mb, sz);
            bulk_g2s(s2u(tbl + buf * (NTAB * NNODES)),
                     g_table + (size_t)(start + an) * NNODES, sz, mb);
        }
    }

    float* op = out + (size_t)g * K_GRID;
    #pragma unroll
    for (int q = 0; q < PPT; q++)
        atomicAdd(&op[kb + q * BLOCK], st.acc[q]);
}

// ---------------------------------------------------------------------------
extern "C" void kernel_launch(void* const* d_in, const int* in_sizes, int n_in,
                              void* d_out, int out_size) {
    const float* coeff      = (const float*)d_in[0];
    const float* atom_coord = (const float*)d_in[1];
    const float* grid       = (const float*)d_in[2];
    const int*   batch_raw  = (const int*)d_in[3];
    float* out = (float*)d_out;

    static bool attr_done = false;
    if (!attr_done) {
        cudaFuncSetAttribute(density_kernel,
                             cudaFuncAttributeMaxDynamicSharedMemorySize,
                             SMEM_DYN);
        attr_done = true;
    }

    build_kernel<<<N_ATOMS, 128>>>(coeff, batch_raw, out);
    density_kernel<<<dim3(NCHUNK, N_GRAPHS, ASPLIT), BLOCK, SMEM_DYN>>>(
        atom_coord, grid, out);
}